// round 2
// baseline (speedup 1.0000x reference)
#include <cuda_runtime.h>
#include <cstdint>

// Problem constants
// B=4, S=2048, D=1024, H=16, depth=64
static constexpr int BB   = 4;
static constexpr int SS   = 2048;
static constexpr int DD   = 1024;
static constexpr int HH   = 16;
static constexpr int DEP  = 64;
static constexpr size_t OUT_ELEMS  = (size_t)BB * SS * DD;            // 8,388,608
static constexpr size_t ATTN_ELEMS = (size_t)BB * HH * SS * (size_t)SS; // 268,435,456

// Scratch (static device allocations are the sanctioned workaround)
__device__ float g_q[OUT_ELEMS];    // head-major [B,H,S,64]
__device__ float g_k[OUT_ELEMS];
__device__ float g_v[OUT_ELEMS];
__device__ float g_rep[OUT_ELEMS];  // concat layout [B,S,D]
__device__ float g_attn_fb[ATTN_ELEMS]; // fallback if attn is not part of d_out

// ---------------------------------------------------------------------------
// GEMM 1: projections  Y = X @ W + b, output scattered to head-major [B,H,S,64]
// M = B*S = 8192, N = D = 1024, K = D = 1024
// Tile 64x64x16, 256 threads, 4x4 per-thread micro-tile
// ---------------------------------------------------------------------------
__global__ __launch_bounds__(256) void gemm_proj(
    const float* __restrict__ X, const float* __restrict__ W,
    const float* __restrict__ bias, float* __restrict__ O)
{
    __shared__ float As[16][65];  // padded (transposed store)
    __shared__ float Bs[16][64];
    const int m0 = blockIdx.y * 64, n0 = blockIdx.x * 64;
    const int tid = threadIdx.x, tx = tid & 15, ty = tid >> 4;
    float acc[4][4] = {};

    for (int k0 = 0; k0 < 1024; k0 += 16) {
        #pragma unroll
        for (int r = 0; r < 4; r++) {
            int l = tid + r * 256;
            int row = l >> 4, col = l & 15;
            As[col][row] = X[(size_t)(m0 + row) * 1024 + k0 + col];
        }
        #pragma unroll
        for (int r = 0; r < 4; r++) {
            int l = tid + r * 256;
            int kk = l >> 6, nn = l & 63;
            Bs[kk][nn] = W[(size_t)(k0 + kk) * 1024 + n0 + nn];
        }
        __syncthreads();
        #pragma unroll
        for (int kk = 0; kk < 16; kk++) {
            float a[4], b[4];
            #pragma unroll
            for (int i = 0; i < 4; i++) a[i] = As[kk][ty * 4 + i];
            float4 bv = *(const float4*)&Bs[kk][tx * 4];
            b[0] = bv.x; b[1] = bv.y; b[2] = bv.z; b[3] = bv.w;
            #pragma unroll
            for (int i = 0; i < 4; i++)
                #pragma unroll
                for (int j = 0; j < 4; j++)
                    acc[i][j] += a[i] * b[j];
        }
        __syncthreads();
    }

    const int n = n0 + tx * 4;
    const int h = n >> 6, dd = n & 63;
    float4 bv4 = *(const float4*)&bias[n];
    #pragma unroll
    for (int i = 0; i < 4; i++) {
        int m = m0 + ty * 4 + i;
        int bidx = m >> 11, s = m & 2047;
        float4 o;
        o.x = acc[i][0] + bv4.x;
        o.y = acc[i][1] + bv4.y;
        o.z = acc[i][2] + bv4.z;
        o.w = acc[i][3] + bv4.w;
        size_t idx = (((size_t)(bidx * 16 + h) * 2048) + s) * 64 + dd;
        *(float4*)&O[idx] = o;
    }
}

// ---------------------------------------------------------------------------
// GEMM 2: scores = (q @ k^T) * scale + mask * (-1e9)
// per (b,h): M = N = 2048, K = 64
// ---------------------------------------------------------------------------
__global__ __launch_bounds__(256) void gemm_scores(
    const float* __restrict__ Qh, const float* __restrict__ Kh,
    const float* __restrict__ Mask, float* __restrict__ Attn)
{
    __shared__ float As[16][65];
    __shared__ float Bs[16][65];
    const int bh = blockIdx.z;
    const int b = bh >> 4;
    const float* A  = Qh + (size_t)bh * 2048 * 64;
    const float* Bm = Kh + (size_t)bh * 2048 * 64;
    const float* Mk = Mask + (size_t)b * 2048 * 2048;
    float* Out = Attn + (size_t)bh * 2048 * 2048;

    const int m0 = blockIdx.y * 64, n0 = blockIdx.x * 64;
    const int tid = threadIdx.x, tx = tid & 15, ty = tid >> 4;
    float acc[4][4] = {};

    for (int k0 = 0; k0 < 64; k0 += 16) {
        #pragma unroll
        for (int r = 0; r < 4; r++) {
            int l = tid + r * 256;
            int row = l >> 4, col = l & 15;
            As[col][row] = A[(size_t)(m0 + row) * 64 + k0 + col];
            Bs[col][row] = Bm[(size_t)(n0 + row) * 64 + k0 + col];
        }
        __syncthreads();
        #pragma unroll
        for (int kk = 0; kk < 16; kk++) {
            float a[4], b[4];
            #pragma unroll
            for (int i = 0; i < 4; i++) a[i] = As[kk][ty * 4 + i];
            #pragma unroll
            for (int j = 0; j < 4; j++) b[j] = Bs[kk][tx * 4 + j];
            #pragma unroll
            for (int i = 0; i < 4; i++)
                #pragma unroll
                for (int j = 0; j < 4; j++)
                    acc[i][j] += a[i] * b[j];
        }
        __syncthreads();
    }

    const int n = n0 + tx * 4;
    #pragma unroll
    for (int i = 0; i < 4; i++) {
        int m = m0 + ty * 4 + i;
        float4 mk = *(const float4*)&Mk[(size_t)m * 2048 + n];
        float4 o;
        o.x = acc[i][0] * 0.125f + mk.x * (-1e9f);
        o.y = acc[i][1] * 0.125f + mk.y * (-1e9f);
        o.z = acc[i][2] * 0.125f + mk.z * (-1e9f);
        o.w = acc[i][3] * 0.125f + mk.w * (-1e9f);
        *(float4*)&Out[(size_t)m * 2048 + n] = o;
    }
}

// ---------------------------------------------------------------------------
// Softmax over the last dim (row length 2048), in place. One block per row.
// ---------------------------------------------------------------------------
__global__ __launch_bounds__(256) void softmax_rows(float* __restrict__ Attn)
{
    const size_t r = blockIdx.x;
    float* row = Attn + r * 2048;
    const int tid = threadIdx.x;
    __shared__ float red[8];

    float v[8];
    float mx = -3.4e38f;
    #pragma unroll
    for (int i = 0; i < 8; i++) {
        v[i] = row[tid + i * 256];
        mx = fmaxf(mx, v[i]);
    }
    #pragma unroll
    for (int o = 16; o; o >>= 1) mx = fmaxf(mx, __shfl_xor_sync(0xffffffffu, mx, o));
    if ((tid & 31) == 0) red[tid >> 5] = mx;
    __syncthreads();
    mx = red[0];
    #pragma unroll
    for (int w = 1; w < 8; w++) mx = fmaxf(mx, red[w]);
    __syncthreads();

    float sum = 0.f;
    #pragma unroll
    for (int i = 0; i < 8; i++) {
        v[i] = __expf(v[i] - mx);
        sum += v[i];
    }
    #pragma unroll
    for (int o = 16; o; o >>= 1) sum += __shfl_xor_sync(0xffffffffu, sum, o);
    if ((tid & 31) == 0) red[tid >> 5] = sum;
    __syncthreads();
    float tot = 0.f;
    #pragma unroll
    for (int w = 0; w < 8; w++) tot += red[w];
    const float rinv = 1.0f / tot;
    #pragma unroll
    for (int i = 0; i < 8; i++) row[tid + i * 256] = v[i] * rinv;
}

// ---------------------------------------------------------------------------
// GEMM 3: rep = attn @ v     per (b,h): M = 2048, N = 64, K = 2048
// Output to concat layout [B,S,D]
// ---------------------------------------------------------------------------
__global__ __launch_bounds__(256) void gemm_rep(
    const float* __restrict__ Attn, const float* __restrict__ Vh,
    float* __restrict__ O)
{
    __shared__ float As[16][65];
    __shared__ float Bs[16][64];
    const int bh = blockIdx.z;
    const int b = bh >> 4, h = bh & 15;
    const float* A  = Attn + (size_t)bh * 2048 * 2048;
    const float* Bm = Vh + (size_t)bh * 2048 * 64;

    const int m0 = blockIdx.y * 64;
    const int tid = threadIdx.x, tx = tid & 15, ty = tid >> 4;
    float acc[4][4] = {};

    for (int k0 = 0; k0 < 2048; k0 += 16) {
        #pragma unroll
        for (int r = 0; r < 4; r++) {
            int l = tid + r * 256;
            int row = l >> 4, col = l & 15;
            As[col][row] = A[(size_t)(m0 + row) * 2048 + k0 + col];
        }
        #pragma unroll
        for (int r = 0; r < 4; r++) {
            int l = tid + r * 256;
            int kk = l >> 6, nn = l & 63;
            Bs[kk][nn] = Bm[(size_t)(k0 + kk) * 64 + nn];
        }
        __syncthreads();
        #pragma unroll
        for (int kk = 0; kk < 16; kk++) {
            float a[4], b[4];
            #pragma unroll
            for (int i = 0; i < 4; i++) a[i] = As[kk][ty * 4 + i];
            float4 bv = *(const float4*)&Bs[kk][tx * 4];
            b[0] = bv.x; b[1] = bv.y; b[2] = bv.z; b[3] = bv.w;
            #pragma unroll
            for (int i = 0; i < 4; i++)
                #pragma unroll
                for (int j = 0; j < 4; j++)
                    acc[i][j] += a[i] * b[j];
        }
        __syncthreads();
    }

    const int dd = tx * 4;
    #pragma unroll
    for (int i = 0; i < 4; i++) {
        int s = m0 + ty * 4 + i;
        float4 o;
        o.x = acc[i][0]; o.y = acc[i][1]; o.z = acc[i][2]; o.w = acc[i][3];
        size_t idx = ((size_t)(b * 2048 + s)) * 1024 + h * 64 + dd;
        *(float4*)&O[idx] = o;
    }
}

// ---------------------------------------------------------------------------
// GEMM 4: out = rep @ Wo + bo   (plain [M,N] output)
// ---------------------------------------------------------------------------
__global__ __launch_bounds__(256) void gemm_out(
    const float* __restrict__ X, const float* __restrict__ W,
    const float* __restrict__ bias, float* __restrict__ O)
{
    __shared__ float As[16][65];
    __shared__ float Bs[16][64];
    const int m0 = blockIdx.y * 64, n0 = blockIdx.x * 64;
    const int tid = threadIdx.x, tx = tid & 15, ty = tid >> 4;
    float acc[4][4] = {};

    for (int k0 = 0; k0 < 1024; k0 += 16) {
        #pragma unroll
        for (int r = 0; r < 4; r++) {
            int l = tid + r * 256;
            int row = l >> 4, col = l & 15;
            As[col][row] = X[(size_t)(m0 + row) * 1024 + k0 + col];
        }
        #pragma unroll
        for (int r = 0; r < 4; r++) {
            int l = tid + r * 256;
            int kk = l >> 6, nn = l & 63;
            Bs[kk][nn] = W[(size_t)(k0 + kk) * 1024 + n0 + nn];
        }
        __syncthreads();
        #pragma unroll
        for (int kk = 0; kk < 16; kk++) {
            float a[4], b[4];
            #pragma unroll
            for (int i = 0; i < 4; i++) a[i] = As[kk][ty * 4 + i];
            float4 bv = *(const float4*)&Bs[kk][tx * 4];
            b[0] = bv.x; b[1] = bv.y; b[2] = bv.z; b[3] = bv.w;
            #pragma unroll
            for (int i = 0; i < 4; i++)
                #pragma unroll
                for (int j = 0; j < 4; j++)
                    acc[i][j] += a[i] * b[j];
        }
        __syncthreads();
    }

    const int n = n0 + tx * 4;
    float4 bv4 = *(const float4*)&bias[n];
    #pragma unroll
    for (int i = 0; i < 4; i++) {
        int m = m0 + ty * 4 + i;
        float4 o;
        o.x = acc[i][0] + bv4.x;
        o.y = acc[i][1] + bv4.y;
        o.z = acc[i][2] + bv4.z;
        o.w = acc[i][3] + bv4.w;
        *(float4*)&O[(size_t)m * 1024 + n] = o;
    }
}

// ---------------------------------------------------------------------------
// Launch
// ---------------------------------------------------------------------------
extern "C" void kernel_launch(void* const* d_in, const int* in_sizes, int n_in,
                              void* d_out, int out_size)
{
    const float* Q    = (const float*)d_in[0];
    const float* K    = (const float*)d_in[1];
    const float* V    = (const float*)d_in[2];
    const float* Mask = (const float*)d_in[3];
    const float* Wq   = (const float*)d_in[4];
    const float* bq   = (const float*)d_in[5];
    const float* Wk   = (const float*)d_in[6];
    const float* bk   = (const float*)d_in[7];
    const float* Wv   = (const float*)d_in[8];
    const float* bv   = (const float*)d_in[9];
    const float* Wo   = (const float*)d_in[10];
    const float* bo   = (const float*)d_in[11];

    float* out = (float*)d_out;

    float *q, *k, *v, *rep;
    {
        void* p;
        cudaGetSymbolAddress(&p, g_q);   q   = (float*)p;
        cudaGetSymbolAddress(&p, g_k);   k   = (float*)p;
        cudaGetSymbolAddress(&p, g_v);   v   = (float*)p;
        cudaGetSymbolAddress(&p, g_rep); rep = (float*)p;
    }
    float* attn;
    if ((size_t)out_size >= OUT_ELEMS + ATTN_ELEMS) {
        attn = out + OUT_ELEMS;            // attn is the second output region
    } else {
        void* p;
        cudaGetSymbolAddress(&p, g_attn_fb);
        attn = (float*)p;
    }

    dim3 gproj(16, 128);                   // N/64 x M/64  (M=8192, N=1024)
    gemm_proj<<<gproj, 256>>>(Q, Wq, bq, q);
    gemm_proj<<<gproj, 256>>>(K, Wk, bk, k);
    gemm_proj<<<gproj, 256>>>(V, Wv, bv, v);

    dim3 gsc(32, 32, BB * HH);             // 2048/64 x 2048/64 x 64
    gemm_scores<<<gsc, 256>>>(q, k, Mask, attn);

    softmax_rows<<<BB * HH * SS, 256>>>(attn);

    dim3 grep(1, 32, BB * HH);             // N=64 -> 1 tile
    gemm_rep<<<grep, 256>>>(attn, v, rep);

    gemm_out<<<gproj, 256>>>(rep, Wo, bo, out);
}

// round 4
// speedup vs baseline: 2.6302x; 2.6302x over previous
#include <cuda_runtime.h>
#include <cstdint>

// B=4, S=2048, D=1024, H=16, depth=64
static constexpr int BBc = 4;
static constexpr int SSc = 2048;
static constexpr int HHc = 16;
static constexpr size_t OUT_ELEMS  = (size_t)8388608;    // B*S*D
static constexpr size_t ATTN_ELEMS = (size_t)268435456;  // B*H*S*S

// Static scratch
__device__ float g_q[OUT_ELEMS];          // [B*H][2048][64]
__device__ float g_k[OUT_ELEMS];          // [B*H][2048][64]
__device__ float g_vT[OUT_ELEMS];         // [B*H][64][2048]
__device__ float g_rep[OUT_ELEMS];        // [B,S,D] concat
__device__ float g_wt[4][1024 * 1024];    // transposed weights [n][k]
__device__ float g_attn_fb[ATTN_ELEMS];   // fallback

__device__ __forceinline__ uint32_t smem_u32(const void* p) {
    uint32_t a;
    asm("{ .reg .u64 t; cvta.to.shared.u64 t, %1; cvt.u32.u64 %0, t; }" : "=r"(a) : "l"(p));
    return a;
}
__device__ __forceinline__ uint32_t f2tf32(float f) {
    uint32_t r;
    asm("cvt.rna.tf32.f32 %0, %1;" : "=r"(r) : "f"(f));
    return r;
}

// ---------------------------------------------------------------------------
// Weight transpose: wt[n][k] = W[k][n], 1024x1024
// ---------------------------------------------------------------------------
__global__ __launch_bounds__(256) void transpose1024(const float* __restrict__ in,
                                                     float* __restrict__ out) {
    __shared__ float t[32][33];
    int x = blockIdx.x * 32 + threadIdx.x;
    int y = blockIdx.y * 32 + threadIdx.y;
    #pragma unroll
    for (int j = 0; j < 32; j += 8)
        t[threadIdx.y + j][threadIdx.x] = in[(size_t)(y + j) * 1024 + x];
    __syncthreads();
    x = blockIdx.y * 32 + threadIdx.x;
    y = blockIdx.x * 32 + threadIdx.y;
    #pragma unroll
    for (int j = 0; j < 32; j += 8)
        out[(size_t)(y + j) * 1024 + x] = t[threadIdx.x][threadIdx.y + j];
}

// ---------------------------------------------------------------------------
// tf32 mma.sync GEMM: D[m][n] = sum_k A[m][k] * B[n][k]
// Block tile 128 x NT, K-chunk = 32, 8 warps.
//   NT=128: warp grid 2(M)x4(N), warp tile 64x32
//   NT=64 : warp grid 4(M)x2(N), warp tile 32x32
// EPI: 0 head-major+bias | 1 transposed-V+bias | 2 scores(mask) | 3 rep->concat | 4 plain+bias
// ---------------------------------------------------------------------------
template <int NT, int NC, int EPI>
__global__ __launch_bounds__(256) void mma_gemm(
    const float* __restrict__ Abase, int lda, long aBS,
    const float* __restrict__ Bbase, int ldb, long bBS,
    const float* __restrict__ bias, const float* __restrict__ mask,
    float* __restrict__ obase)
{
    constexpr int WM  = (NT == 128) ? 2 : 4;
    constexpr int WN  = 8 / WM;
    constexpr int WTM = 128 / WM;     // 64 or 32
    constexpr int WTN = NT / WN;      // 32
    constexpr int MT  = WTM / 16;     // 4 or 2
    constexpr int NTt = WTN / 8;      // 4
    constexpr int BP  = NT / 32;      // B row-groups per thread

    extern __shared__ char smem[];
    const int tid = threadIdx.x, lane = tid & 31, warp = tid >> 5;
    const int wm = warp / WN, wn = warp % WN;
    const int z = blockIdx.z;
    const int m0 = blockIdx.y * 128, n0 = blockIdx.x * NT;
    const float* A = Abase + (size_t)z * aBS;
    const float* B = Bbase + (size_t)z * bBS;

    uint32_t sb = smem_u32(smem);
    const uint32_t AsB[2] = { sb, sb + 16384u };
    const uint32_t BsB[2] = { sb + 32768u, sb + 32768u + (uint32_t)NT * 128u };

    float c[MT][NTt][4] = {};

    const int lrow = tid >> 3, lseg = tid & 7;
    float4 ar[4], br[BP];

    // preload chunk 0
    #pragma unroll
    for (int p = 0; p < 4; ++p)
        ar[p] = *(const float4*)(A + (size_t)(m0 + lrow + p * 32) * lda + lseg * 4);
    #pragma unroll
    for (int p = 0; p < BP; ++p)
        br[p] = *(const float4*)(B + (size_t)(n0 + lrow + p * 32) * ldb + lseg * 4);
    #pragma unroll
    for (int p = 0; p < 4; ++p) {
        int r = lrow + p * 32;
        uint32_t d = AsB[0] + (uint32_t)(r * 128) + (uint32_t)((lseg ^ (r & 7)) << 4);
        asm volatile("st.shared.v4.b32 [%0], {%1,%2,%3,%4};" :: "r"(d),
            "r"(f2tf32(ar[p].x)), "r"(f2tf32(ar[p].y)),
            "r"(f2tf32(ar[p].z)), "r"(f2tf32(ar[p].w)) : "memory");
    }
    #pragma unroll
    for (int p = 0; p < BP; ++p) {
        int r = lrow + p * 32;
        uint32_t d = BsB[0] + (uint32_t)(r * 128) + (uint32_t)((lseg ^ (r & 7)) << 4);
        asm volatile("st.shared.v4.b32 [%0], {%1,%2,%3,%4};" :: "r"(d),
            "r"(f2tf32(br[p].x)), "r"(f2tf32(br[p].y)),
            "r"(f2tf32(br[p].z)), "r"(f2tf32(br[p].w)) : "memory");
    }

    #pragma unroll 1
    for (int ci = 0; ci < NC; ++ci) {
        __syncthreads();
        if (ci + 1 < NC) {
            #pragma unroll
            for (int p = 0; p < 4; ++p)
                ar[p] = *(const float4*)(A + (size_t)(m0 + lrow + p * 32) * lda
                                         + (ci + 1) * 32 + lseg * 4);
            #pragma unroll
            for (int p = 0; p < BP; ++p)
                br[p] = *(const float4*)(B + (size_t)(n0 + lrow + p * 32) * ldb
                                         + (ci + 1) * 32 + lseg * 4);
        }
        const int buf = ci & 1;
        #pragma unroll
        for (int ks = 0; ks < 4; ++ks) {
            uint32_t a[MT][4];
            #pragma unroll
            for (int mt = 0; mt < MT; ++mt) {
                int row = wm * WTM + mt * 16 + (lane & 15);
                int seg = ks * 2 + (lane >> 4);
                uint32_t addr = AsB[buf] + (uint32_t)(row * 128)
                              + (uint32_t)((seg ^ (row & 7)) << 4);
                asm volatile("ldmatrix.sync.aligned.m8n8.x4.shared.b16 {%0,%1,%2,%3}, [%4];"
                    : "=r"(a[mt][0]), "=r"(a[mt][1]), "=r"(a[mt][2]), "=r"(a[mt][3])
                    : "r"(addr));
            }
            #pragma unroll
            for (int nt = 0; nt < NTt; ++nt) {
                int nl = wn * WTN + nt * 8 + (lane >> 2);
                uint32_t b0a = BsB[buf] + (uint32_t)(nl * 128)
                             + (uint32_t)((((ks * 2) ^ (nl & 7)) << 4) + (lane & 3) * 4);
                uint32_t b1a = BsB[buf] + (uint32_t)(nl * 128)
                             + (uint32_t)((((ks * 2 + 1) ^ (nl & 7)) << 4) + (lane & 3) * 4);
                uint32_t b0, b1;
                asm volatile("ld.shared.b32 %0, [%1];" : "=r"(b0) : "r"(b0a));
                asm volatile("ld.shared.b32 %0, [%1];" : "=r"(b1) : "r"(b1a));
                #pragma unroll
                for (int mt = 0; mt < MT; ++mt) {
                    asm volatile(
                        "mma.sync.aligned.m16n8k8.row.col.f32.tf32.tf32.f32 "
                        "{%0,%1,%2,%3}, {%4,%5,%6,%7}, {%8,%9}, {%0,%1,%2,%3};"
                        : "+f"(c[mt][nt][0]), "+f"(c[mt][nt][1]),
                          "+f"(c[mt][nt][2]), "+f"(c[mt][nt][3])
                        : "r"(a[mt][0]), "r"(a[mt][1]), "r"(a[mt][2]), "r"(a[mt][3]),
                          "r"(b0), "r"(b1));
                }
            }
        }
        if (ci + 1 < NC) {
            const int nb = (ci + 1) & 1;
            #pragma unroll
            for (int p = 0; p < 4; ++p) {
                int r = lrow + p * 32;
                uint32_t d = AsB[nb] + (uint32_t)(r * 128) + (uint32_t)((lseg ^ (r & 7)) << 4);
                asm volatile("st.shared.v4.b32 [%0], {%1,%2,%3,%4};" :: "r"(d),
                    "r"(f2tf32(ar[p].x)), "r"(f2tf32(ar[p].y)),
                    "r"(f2tf32(ar[p].z)), "r"(f2tf32(ar[p].w)) : "memory");
            }
            #pragma unroll
            for (int p = 0; p < BP; ++p) {
                int r = lrow + p * 32;
                uint32_t d = BsB[nb] + (uint32_t)(r * 128) + (uint32_t)((lseg ^ (r & 7)) << 4);
                asm volatile("st.shared.v4.b32 [%0], {%1,%2,%3,%4};" :: "r"(d),
                    "r"(f2tf32(br[p].x)), "r"(f2tf32(br[p].y)),
                    "r"(f2tf32(br[p].z)), "r"(f2tf32(br[p].w)) : "memory");
            }
        }
    }

    // ---- Epilogue ----
    const int mwb = m0 + wm * WTM;
    const int nwb = n0 + wn * WTN;
    #pragma unroll
    for (int mt = 0; mt < MT; ++mt) {
        #pragma unroll
        for (int nt = 0; nt < NTt; ++nt) {
            const int mr = mwb + mt * 16 + (lane >> 2);
            const int nc = nwb + nt * 8 + 2 * (lane & 3);
            float v0 = c[mt][nt][0], v1 = c[mt][nt][1];
            float v2 = c[mt][nt][2], v3 = c[mt][nt][3];

            if constexpr (EPI == 0) {          // head-major + bias
                float2 bb = *(const float2*)(bias + nc);
                int h = nc >> 6, dd = nc & 63;
                int b = mr >> 11, s = mr & 2047;
                float2 o0 = { v0 + bb.x, v1 + bb.y };
                float2 o1 = { v2 + bb.x, v3 + bb.y };
                *(float2*)(obase + (((size_t)(b * HHc + h) * 2048 + s) * 64 + dd)) = o0;
                *(float2*)(obase + (((size_t)(b * HHc + h) * 2048 + (s + 8)) * 64 + dd)) = o1;
            } else if constexpr (EPI == 1) {   // transposed V: [bh][dd][s]
                float2 bb = *(const float2*)(bias + nc);
                int h = nc >> 6, dd = nc & 63;
                int b = mr >> 11, s = mr & 2047;
                size_t base = ((size_t)(b * HHc + h) * 64 + dd) * 2048;
                obase[base + s] = v0 + bb.x;
                obase[base + 2048 + s] = v1 + bb.y;
                obase[base + s + 8] = v2 + bb.x;
                obase[base + 2048 + s + 8] = v3 + bb.y;
            } else if constexpr (EPI == 2) {   // scores: *0.125 + mask*(-1e9)
                const float* Mk = mask + (size_t)(z >> 4) * SSc * SSc;
                float* o = obase + (size_t)z * SSc * SSc;
                float2 mk0 = *(const float2*)(Mk + (size_t)mr * SSc + nc);
                float2 mk1 = *(const float2*)(Mk + (size_t)(mr + 8) * SSc + nc);
                float2 o0 = { v0 * 0.125f + mk0.x * (-1e9f), v1 * 0.125f + mk0.y * (-1e9f) };
                float2 o1 = { v2 * 0.125f + mk1.x * (-1e9f), v3 * 0.125f + mk1.y * (-1e9f) };
                *(float2*)(o + (size_t)mr * SSc + nc) = o0;
                *(float2*)(o + (size_t)(mr + 8) * SSc + nc) = o1;
            } else if constexpr (EPI == 3) {   // rep -> concat [B,S,D]
                int b = z >> 4, h = z & 15;
                float2 o0 = { v0, v1 };
                float2 o1 = { v2, v3 };
                *(float2*)(obase + ((size_t)(b * 2048 + mr)) * 1024 + h * 64 + nc) = o0;
                *(float2*)(obase + ((size_t)(b * 2048 + mr + 8)) * 1024 + h * 64 + nc) = o1;
            } else {                           // plain + bias
                float2 bb = *(const float2*)(bias + nc);
                float2 o0 = { v0 + bb.x, v1 + bb.y };
                float2 o1 = { v2 + bb.x, v3 + bb.y };
                *(float2*)(obase + (size_t)mr * 1024 + nc) = o0;
                *(float2*)(obase + (size_t)(mr + 8) * 1024 + nc) = o1;
            }
        }
    }
}

// ---------------------------------------------------------------------------
// Softmax over rows of length 2048, in place.
// ---------------------------------------------------------------------------
__global__ __launch_bounds__(256) void softmax_rows(float* __restrict__ Attn) {
    const size_t rrow = blockIdx.x;
    float* row = Attn + rrow * 2048;
    const int tid = threadIdx.x;
    __shared__ float red[8];

    float v[8];
    float mx = -3.4e38f;
    #pragma unroll
    for (int i = 0; i < 8; i++) { v[i] = row[tid + i * 256]; mx = fmaxf(mx, v[i]); }
    #pragma unroll
    for (int o = 16; o; o >>= 1) mx = fmaxf(mx, __shfl_xor_sync(0xffffffffu, mx, o));
    if ((tid & 31) == 0) red[tid >> 5] = mx;
    __syncthreads();
    mx = red[0];
    #pragma unroll
    for (int w = 1; w < 8; w++) mx = fmaxf(mx, red[w]);
    __syncthreads();

    float sum = 0.f;
    #pragma unroll
    for (int i = 0; i < 8; i++) { v[i] = __expf(v[i] - mx); sum += v[i]; }
    #pragma unroll
    for (int o = 16; o; o >>= 1) sum += __shfl_xor_sync(0xffffffffu, sum, o);
    if ((tid & 31) == 0) red[tid >> 5] = sum;
    __syncthreads();
    float tot = 0.f;
    #pragma unroll
    for (int w = 0; w < 8; w++) tot += red[w];
    const float rinv = 1.0f / tot;
    #pragma unroll
    for (int i = 0; i < 8; i++) row[tid + i * 256] = v[i] * rinv;
}

// ---------------------------------------------------------------------------
// Launch
// ---------------------------------------------------------------------------
static constexpr size_t SMEM128 = 2 * 16384 + 2 * 16384;  // 65536
static constexpr size_t SMEM64  = 2 * 16384 + 2 * 8192;   // 49152

extern "C" void kernel_launch(void* const* d_in, const int* in_sizes, int n_in,
                              void* d_out, int out_size)
{
    const float* Q    = (const float*)d_in[0];
    const float* K    = (const float*)d_in[1];
    const float* V    = (const float*)d_in[2];
    const float* Mask = (const float*)d_in[3];
    const float* Wq   = (const float*)d_in[4];
    const float* bq   = (const float*)d_in[5];
    const float* Wk   = (const float*)d_in[6];
    const float* bk   = (const float*)d_in[7];
    const float* Wv   = (const float*)d_in[8];
    const float* bv   = (const float*)d_in[9];
    const float* Wo   = (const float*)d_in[10];
    const float* bo   = (const float*)d_in[11];
    float* out = (float*)d_out;

    float *q, *k, *vT, *rep, *wt;
    {
        void* p;
        cudaGetSymbolAddress(&p, g_q);   q   = (float*)p;
        cudaGetSymbolAddress(&p, g_k);   k   = (float*)p;
        cudaGetSymbolAddress(&p, g_vT);  vT  = (float*)p;
        cudaGetSymbolAddress(&p, g_rep); rep = (float*)p;
        cudaGetSymbolAddress(&p, g_wt);  wt  = (float*)p;
    }
    float* wqT = wt;
    float* wkT = wt + (size_t)1024 * 1024;
    float* wvT = wt + (size_t)2 * 1024 * 1024;
    float* woT = wt + (size_t)3 * 1024 * 1024;

    float* attn;
    if ((size_t)out_size >= OUT_ELEMS + ATTN_ELEMS) {
        attn = out + OUT_ELEMS;
    } else {
        void* p;
        cudaGetSymbolAddress(&p, g_attn_fb);
        attn = (float*)p;
    }

    cudaFuncSetAttribute(mma_gemm<128, 32, 0>, cudaFuncAttributeMaxDynamicSharedMemorySize, SMEM128);
    cudaFuncSetAttribute(mma_gemm<128, 32, 1>, cudaFuncAttributeMaxDynamicSharedMemorySize, SMEM128);
    cudaFuncSetAttribute(mma_gemm<128, 2, 2>,  cudaFuncAttributeMaxDynamicSharedMemorySize, SMEM128);
    cudaFuncSetAttribute(mma_gemm<64, 64, 3>,  cudaFuncAttributeMaxDynamicSharedMemorySize, SMEM64);
    cudaFuncSetAttribute(mma_gemm<128, 32, 4>, cudaFuncAttributeMaxDynamicSharedMemorySize, SMEM128);

    // Transpose weights -> [n][k]
    dim3 tb(32, 8), tg(32, 32);
    transpose1024<<<tg, tb>>>(Wq, wqT);
    transpose1024<<<tg, tb>>>(Wk, wkT);
    transpose1024<<<tg, tb>>>(Wv, wvT);
    transpose1024<<<tg, tb>>>(Wo, woT);

    // Projections (M=8192, N=1024, K=1024)
    dim3 gp(8, 64, 1);
    mma_gemm<128, 32, 0><<<gp, 256, SMEM128>>>(Q, 1024, 0, wqT, 1024, 0, bq, nullptr, q);
    mma_gemm<128, 32, 0><<<gp, 256, SMEM128>>>(K, 1024, 0, wkT, 1024, 0, bk, nullptr, k);
    mma_gemm<128, 32, 1><<<gp, 256, SMEM128>>>(V, 1024, 0, wvT, 1024, 0, bv, nullptr, vT);

    // Scores (per bh: 2048x2048, K=64) + mask
    dim3 gs(16, 16, BBc * HHc);
    mma_gemm<128, 2, 2><<<gs, 256, SMEM128>>>(q, 64, (long)2048 * 64,
                                              k, 64, (long)2048 * 64,
                                              nullptr, Mask, attn);

    softmax_rows<<<BBc * HHc * SSc, 256>>>(attn);

    // rep = attn @ v  (per bh: M=2048, N=64, K=2048), B = vT
    dim3 gr(1, 16, BBc * HHc);
    mma_gemm<64, 64, 3><<<gr, 256, SMEM64>>>(attn, 2048, (long)SSc * SSc,
                                             vT, 2048, (long)64 * 2048,
                                             nullptr, nullptr, rep);

    // out = rep @ Wo + bo
    mma_gemm<128, 32, 4><<<gp, 256, SMEM128>>>(rep, 1024, 0, woT, 1024, 0, bo, nullptr, out);
}